// round 4
// baseline (speedup 1.0000x reference)
#include <cuda_runtime.h>
#include <math.h>

// ---------------------------------------------------------------------------
// OneDimEquivalent scan, time-chunked (16 chunks x 256 steps, 256 warm-up).
//   s = k^2 + u^2 ; g(s) = (1/sqrt(2pi)) \int sech^2(sqrt(s) z) e^{-z^2/2} dz
//   v' = 0.8 v + 0.2 u ; k' = 0.8 k + g*(0.28 k + 0.52 v') ; z = 2.1 k'
// Contraction (~0.95/step) makes 256 warm-up steps sufficient (~2e-6).
// 512 blocks, 4/SM single wave. g LUT: 4096 cells of line coeffs (a,b);
// g = fma(t, a, b) with t = 64*s. Chain: FMA -> IMAD -> LDS.64 -> FMA -> FMA.
// ---------------------------------------------------------------------------

#define B_DIM 4096
#define T_DIM 4096
#define CHUNKS 16
#define LCH 256               // steps written per chunk
#define WARM 256              // warm-up steps for chunks c>0
#define TBL_N 4096
#define SCALE_S 64.0f         // index t = 64*s ; covers s in [0, 64]
#define SQRT_SCALE 8.0f       // sqrt(64)
#define VC_CONST 4.16f        // 0.52*8
#define ZC_CONST 0.2625f      // 2.1/8
#define MAGIC 12582912.0f     // 1.5 * 2^23
#define UUS_CAP 3900.0f       // off-chain clamp on 64*u^2
#define INV_SQRT_2PI 0.3989422804014327f
#define NQ 96                 // trapezoid intervals on [0, 5]

__device__ float  g_qw[NQ + 1];
__device__ float  g_val[TBL_N];
__device__ float2 g_tab[TBL_N];   // (a, b): g ~= a*t + b on cell

// ---------------------------------------------------------------------------
__global__ void qw_kernel() {
    int j = threadIdx.x;
    if (j > NQ) return;
    const float h = 5.0f / (float)NQ;
    float z = h * (float)j;
    float w = (j == 0 || j == NQ) ? 0.5f * h : h;
    g_qw[j] = 2.0f * INV_SQRT_2PI * w * __expf(-0.5f * z * z);
}

// table values g(s_i), s_i = i/64 ; sech^2(x) = 4 e^{-2x}/(1+e^{-2x})^2
__global__ void table_val_kernel() {
    int i = blockIdx.x * blockDim.x + threadIdx.x;
    if (i >= TBL_N) return;
    float s = (float)i * (1.0f / SCALE_S);
    float d = sqrtf(s);
    const float h = 5.0f / (float)NQ;
    float dz = d * h;
    float x = 0.0f;
    float acc = 0.0f;
    #pragma unroll 4
    for (int j = 0; j <= NQ; ++j) {
        float e = __expf(-2.0f * x);
        float inv = __fdividef(1.0f, 1.0f + e);
        acc = fmaf(g_qw[j], 4.0f * e * inv * inv, acc);
        x += dz;
    }
    g_val[i] = acc;
}

// line coefficients: a = centered slope per index, b = val - a*i
__global__ void table_coef_kernel() {
    int i = blockIdx.x * blockDim.x + threadIdx.x;
    if (i >= TBL_N) return;
    float a;
    if (i == 0)              a = g_val[1] - g_val[0];
    else if (i == TBL_N - 1) a = g_val[TBL_N - 1] - g_val[TBL_N - 2];
    else                     a = 0.5f * (g_val[i + 1] - g_val[i - 1]);
    g_tab[i].x = a;
    g_tab[i].y = g_val[i] - a * (float)i;
}

// ---------------------------------------------------------------------------
// Scan: grid (32 rowblocks, 16 chunks) x 128 threads. 4 blocks/SM.
// Shared: coeff table (32KB) + per-warp staging (stride 33, 17KB).
// State pre-scaled K = 8*k so index t = fma(K,K,uus).
// ---------------------------------------------------------------------------
__global__ __launch_bounds__(128, 4)
void scan_kernel(const float* __restrict__ u, float* __restrict__ out) {
    extern __shared__ float smem[];
    float2* s_tab = (float2*)smem;             // 4096 float2
    float*  s_out = smem + 2 * TBL_N;          // 128 * 33 floats

    {   // cooperative table load
        const float4* gt = (const float4*)g_tab;
        float4* st = (float4*)s_tab;
        #pragma unroll 4
        for (int i = threadIdx.x; i < TBL_N / 2; i += 128) st[i] = gt[i];
    }
    __syncthreads();

    const int tid   = threadIdx.x;
    const int lane  = tid & 31;
    const int wbase = tid & ~31;
    const int rowblk = blockIdx.x;
    const int c      = blockIdx.y;
    const int row    = rowblk * 128 + tid;

    // magic addressing: bits(idx + MAGIC)*8 mod 2^32 = 0x5A000000 + 8*idx
    const unsigned tbase = (unsigned)__cvta_generic_to_shared(s_tab) - 0x5A000000u;

    const int t0 = c * LCH - (c ? WARM : 0);   // first simulated step
    const float* urow = u + (size_t)row * T_DIM + t0;
    if (c == 0) out[(size_t)row * (T_DIM + 1)] = 0.0f;

    float* srow = s_out + tid * 33;

    float K = 0.0f, v = 0.0f;                  // K = 8*k
    float ua[32], ub[32];

    auto loadch = [&](float (&b)[32], int grp) {
        const float4* p = (const float4*)(urow + grp * 32);
        #pragma unroll
        for (int q = 0; q < 8; ++q) {
            float4 t = p[q];
            b[4*q+0] = t.x; b[4*q+1] = t.y; b[4*q+2] = t.z; b[4*q+3] = t.w;
        }
    };

    auto step = [&](float uu) {
        float us   = uu * SQRT_SCALE;
        float uus  = fminf(us * us, UUS_CAP);   // off-chain
        float uusM = uus + MAGIC;               // off-chain
        v = fmaf(0.8f, v, 0.2f * uu);           // independent 4-cyc chain
        float vc  = v * VC_CONST;               // 0.52*8*v'
        float w   = fmaf(0.28f, K, vc);         // parallel with index chain
        float K08 = 0.8f * K;                   // parallel
        float tf  = fmaf(K, K, uusM);           // rounded index + MAGIC
        float t   = fmaf(K, K, uus);            // unrounded index (parallel)
        unsigned addr = __float_as_uint(tf) * 8u + tbase;
        float a, b2;
        asm volatile("ld.shared.v2.f32 {%0,%1}, [%2];"
                     : "=f"(a), "=f"(b2) : "r"(addr));
        float g = fmaf(t, a, b2);
        K = fmaf(g, w, K08);                    // K' = 8*k'
    };

    auto computeN = [&](const float (&b)[32]) {   // warm-up: no writes
        #pragma unroll
        for (int j = 0; j < 32; ++j) step(b[j]);
    };

    auto computeW = [&](const float (&b)[32], int grp) {  // write phase
        #pragma unroll
        for (int j = 0; j < 32; ++j) {
            step(b[j]);
            srow[j] = K * ZC_CONST;             // z = 2.1*k'
        }
        __syncwarp();
        int tg = t0 + grp * 32;                 // global start time of group
        #pragma unroll 4
        for (int jr = 0; jr < 32; ++jr) {
            int lr = wbase + jr;
            int grow = rowblk * 128 + lr;
            out[(size_t)grow * (T_DIM + 1) + 1 + tg + lane] = s_out[lr * 33 + lane];
        }
        __syncwarp();
    };

    const int nwarm_g = c ? (WARM / 32) : 0;    // 8 or 0
    const int nend_g  = nwarm_g + LCH / 32;     // +8

    loadch(ua, 0);
    int grp = 0;
    #pragma unroll 1
    for (; grp < nwarm_g; grp += 2) {           // warm-up (even group count)
        loadch(ub, grp + 1);
        computeN(ua);
        loadch(ua, grp + 2);                    // preloads next / first write
        computeN(ub);
    }
    #pragma unroll 1
    for (; grp < nend_g; grp += 2) {            // write phase
        loadch(ub, grp + 1);
        computeW(ua, grp);
        if (grp + 2 < nend_g) loadch(ua, grp + 2);
        computeW(ub, grp + 1);
    }
}

// ---------------------------------------------------------------------------
extern "C" void kernel_launch(void* const* d_in, const int* in_sizes, int n_in,
                              void* d_out, int out_size) {
    const float* u = (const float*)d_in[0];
    float* out = (float*)d_out;

    static const int smem_bytes =
        2 * TBL_N * (int)sizeof(float) + 128 * 33 * (int)sizeof(float);
    cudaFuncSetAttribute(scan_kernel, cudaFuncAttributeMaxDynamicSharedMemorySize, smem_bytes);

    qw_kernel<<<1, 128>>>();
    table_val_kernel<<<TBL_N / 256, 256>>>();
    table_coef_kernel<<<TBL_N / 256, 256>>>();
    scan_kernel<<<dim3(B_DIM / 128, CHUNKS), 128, smem_bytes>>>(u, out);
}

// round 7
// speedup vs baseline: 1.0913x; 1.0913x over previous
#include <cuda_runtime.h>
#include <math.h>

// ---------------------------------------------------------------------------
// OneDimEquivalent scan, time-chunked (16 chunks x 256 steps, 256 warm-up).
//   v' = 0.8 v + 0.2 u ; k' = 0.8 k + g(k^2+u^2)*(0.28 k + 0.52 v') ; z = 2.1 k'
//   g(s) = (1/sqrt(2pi)) \int sech^2(sqrt(s) z) e^{-z^2/2} dz
// g indexed in y = rsqrt(1 + s) (bounded curvature -> 128 cells), stored as
// line coeffs (a,b) LANE-REPLICATED 32x in smem so the per-step gather is a
// ZERO-CONFLICT LDS.64. x is clamped to [1, 85] so the magic-rounded index is
// PROVABLY in [0, 127] -> every shared address in-bounds (no trap possible).
// Chain: FMA -> FMNMX -> MUFU.RSQ -> FMA -> IMAD -> LDS.64 -> FMA -> FMA.
// 512 blocks, 4/SM, single wave.
// ---------------------------------------------------------------------------

#define B_DIM 4096
#define T_DIM 4096
#define CHUNKS 16
#define LCH 256               // steps written per chunk
#define WARM 256              // warm-up steps for chunks c>0
#define TBL_N 128             // cells in y-coordinate
#define CM 142.4f             // t = CM*y + CA maps y in [0.108, 1] -> [0, 127]
#define CA (-15.38f)
#define MAGIC 12582912.0f     // 1.5 * 2^23
#define CAM (CA + MAGIC)
#define X_CAP 85.0f           // clamp on x = k^2 + u^2 + 1  (y >= 0.1084 -> t >= 0.06)
#define UP_CAP 65.0f          // off-chain clamp on u^2 + 1
#define INV_SQRT_2PI 0.3989422804014327f
#define NQ 96                 // trapezoid intervals on [0, 5]

__device__ float  g_qw[NQ + 1];
__device__ float  g_val[TBL_N];
__device__ float2 g_tab[TBL_N];   // (a, b): g ~= a*t + b, t = CM*y + CA

// ---------------------------------------------------------------------------
__global__ void qw_kernel() {
    int j = threadIdx.x;
    if (j > NQ) return;
    const float h = 5.0f / (float)NQ;
    float z = h * (float)j;
    float w = (j == 0 || j == NQ) ? 0.5f * h : h;
    g_qw[j] = 2.0f * INV_SQRT_2PI * w * __expf(-0.5f * z * z);
}

// g at node i: y_i = (i - CA)/CM, s_i = 1/y_i^2 - 1
__global__ void table_val_kernel() {
    int i = threadIdx.x;
    if (i >= TBL_N) return;
    float y = ((float)i - CA) / CM;
    float s = 1.0f / (y * y) - 1.0f;
    if (s < 0.0f) s = 0.0f;
    float d = sqrtf(s);
    const float h = 5.0f / (float)NQ;
    float dz = d * h;
    float x = 0.0f;
    float acc = 0.0f;
    #pragma unroll 4
    for (int j = 0; j <= NQ; ++j) {
        float e = __expf(-2.0f * x);
        float inv = __fdividef(1.0f, 1.0f + e);
        acc = fmaf(g_qw[j], 4.0f * e * inv * inv, acc);
        x += dz;
    }
    g_val[i] = acc;
}

// line coefficients in t: a = centered slope per index, b = val - a*i
__global__ void table_coef_kernel() {
    int i = threadIdx.x;
    if (i >= TBL_N) return;
    float a;
    if (i == 0)              a = g_val[1] - g_val[0];
    else if (i == TBL_N - 1) a = g_val[TBL_N - 1] - g_val[TBL_N - 2];
    else                     a = 0.5f * (g_val[i + 1] - g_val[i - 1]);
    g_tab[i].x = a;
    g_tab[i].y = g_val[i] - a * (float)i;
}

// ---------------------------------------------------------------------------
// Scan: grid (32 rowblocks, 16 chunks) x 128 threads. 4 blocks/SM, 1 wave.
// Shared: lane-replicated coeff table float2[128][32] (32KB) + staging (17KB).
// ---------------------------------------------------------------------------
__global__ __launch_bounds__(128, 4)
void scan_kernel(const float* __restrict__ u, float* __restrict__ out) {
    extern __shared__ float smem[];
    float2* s_tab = (float2*)smem;             // [128][32] float2
    float*  s_out = smem + 2 * TBL_N * 32;     // 128 * 33 floats

    {   // replicate table: entry idx -> 32 lane copies
        float4* st = (float4*)s_tab;           // 2048 float4 (2 lanes each)
        #pragma unroll 4
        for (int e = threadIdx.x; e < TBL_N * 16; e += 128) {
            float2 c = __ldg(&g_tab[e >> 4]);
            st[e] = make_float4(c.x, c.y, c.x, c.y);
        }
    }
    __syncthreads();

    const int tid   = threadIdx.x;
    const int lane  = tid & 31;
    const int wbase = tid & ~31;
    const int rowblk = blockIdx.x;
    const int c      = blockIdx.y;
    const int row    = rowblk * 128 + tid;

    // bits(idx + MAGIC)*256 mod 2^32 = 0x40000000 + 256*idx  (idx in [0,127])
    const unsigned tlane =
        (unsigned)__cvta_generic_to_shared(s_tab) + lane * 8u - 0x40000000u;

    const int t0 = c * LCH - (c ? WARM : 0);
    const float* urow = u + (size_t)row * T_DIM + t0;
    if (c == 0) out[(size_t)row * (T_DIM + 1)] = 0.0f;

    float* srow = s_out + tid * 33;

    float K = 0.0f, v = 0.0f;
    float ua[32], ub[32];

    auto loadch = [&](float (&b)[32], int grp) {
        const float4* p = (const float4*)(urow + grp * 32);
        #pragma unroll
        for (int q = 0; q < 8; ++q) {
            float4 t = p[q];
            b[4*q+0] = t.x; b[4*q+1] = t.y; b[4*q+2] = t.z; b[4*q+3] = t.w;
        }
    };

    auto step = [&](float uu) {
        float up1 = fminf(fmaf(uu, uu, 1.0f), UP_CAP);  // off-chain
        v = fmaf(0.8f, v, 0.2f * uu);                   // own 4-cyc chain
        float w   = fmaf(0.28f, K, 0.52f * v);          // parallel w/ chain
        float K08 = 0.8f * K;                           // parallel
        float x   = fminf(fmaf(K, K, up1), X_CAP);      // chain: x in [1, 85]
        float y;                                        //  -> idx in [0,127]
        asm("rsqrt.approx.f32 %0, %1;" : "=f"(y) : "f"(x));
        float tf = fmaf(y, CM, CAM);                    // rounded idx + MAGIC
        float t  = fmaf(y, CM, CA);                     // unrounded (parallel)
        unsigned addr = __float_as_uint(tf) * 256u + tlane;
        float a, b2;
        asm volatile("ld.shared.v2.f32 {%0,%1}, [%2];"
                     : "=f"(a), "=f"(b2) : "r"(addr));
        float g = fmaf(t, a, b2);
        K = fmaf(g, w, K08);
    };

    auto computeN = [&](const float (&b)[32]) {   // warm-up: no writes
        #pragma unroll
        for (int j = 0; j < 32; ++j) step(b[j]);
    };

    auto computeW = [&](const float (&b)[32], int grp) {  // write phase
        #pragma unroll
        for (int j = 0; j < 32; ++j) {
            step(b[j]);
            srow[j] = 2.1f * K;                 // z = 2.1*k'
        }
        __syncwarp();
        int tg = t0 + grp * 32;
        #pragma unroll 4
        for (int jr = 0; jr < 32; ++jr) {
            int lr = wbase + jr;
            int grow = rowblk * 128 + lr;
            out[(size_t)grow * (T_DIM + 1) + 1 + tg + lane] = s_out[lr * 33 + lane];
        }
        __syncwarp();
    };

    const int nwarm_g = c ? (WARM / 32) : 0;    // 8 or 0
    const int nend_g  = nwarm_g + LCH / 32;     // +8

    loadch(ua, 0);
    int grp = 0;
    #pragma unroll 1
    for (; grp < nwarm_g; grp += 2) {
        loadch(ub, grp + 1);
        computeN(ua);
        loadch(ua, grp + 2);
        computeN(ub);
    }
    #pragma unroll 1
    for (; grp < nend_g; grp += 2) {
        loadch(ub, grp + 1);
        computeW(ua, grp);
        if (grp + 2 < nend_g) loadch(ua, grp + 2);
        computeW(ub, grp + 1);
    }
}

// ---------------------------------------------------------------------------
extern "C" void kernel_launch(void* const* d_in, const int* in_sizes, int n_in,
                              void* d_out, int out_size) {
    const float* u = (const float*)d_in[0];
    float* out = (float*)d_out;

    static const int smem_bytes =
        2 * TBL_N * 32 * (int)sizeof(float) + 128 * 33 * (int)sizeof(float);
    cudaFuncSetAttribute(scan_kernel, cudaFuncAttributeMaxDynamicSharedMemorySize, smem_bytes);

    qw_kernel<<<1, 128>>>();
    table_val_kernel<<<1, TBL_N>>>();
    table_coef_kernel<<<1, TBL_N>>>();
    scan_kernel<<<dim3(B_DIM / 128, CHUNKS), 128, smem_bytes>>>(u, out);
}

// round 8
// speedup vs baseline: 1.3690x; 1.2545x over previous
#include <cuda_runtime.h>
#include <math.h>

// ---------------------------------------------------------------------------
// OneDimEquivalent scan, time-chunked (8 chunks x 512 steps, 192 warm-up).
//   v' = 0.8 v + 0.2 u ; k' = 0.8 k + g(k^2+u^2)*(0.28 k + 0.52 v') ; z = 2.1 k'
// g indexed in y = rsqrt(1+s), 128-cell LUT of line coeffs, lane-replicated
// 32x (zero-conflict LDS.64); x clamped to [1,85] -> index provably in
// [0,127]. R8: u is loaded COALESCED (4 lines per LDG.128 instead of 32) and
// staged through smem; z overwrites u in place (overlay), double-buffered.
// This empties the L1TEX wavefront queue that was inflating on-chain LDS
// latency with occupancy. 256 blocks, 2/SM, single wave, 704 serial steps.
// ---------------------------------------------------------------------------

#define B_DIM 4096
#define T_DIM 4096
#define CHUNKS 8
#define LCH 512               // steps written per chunk
#define WARM 192              // warm-up steps for chunks c>0 (rho^192 ~ 3e-5)
#define TBL_N 128
#define CM 142.4f             // t = CM*y + CA maps y in [0.108, 1] -> [0, 127]
#define CA (-15.38f)
#define MAGIC 12582912.0f     // 1.5 * 2^23
#define CAM (CA + MAGIC)
#define X_CAP 85.0f           // clamp on x = k^2+u^2+1 -> idx in [0,127] always
#define UP_CAP 65.0f          // off-chain clamp on u^2+1
#define INV_SQRT_2PI 0.3989422804014327f
#define NQ 96

__device__ float  g_qw[NQ + 1];
__device__ float  g_val[TBL_N];
__device__ float2 g_tab[TBL_N];   // (a,b): g ~= a*t + b, t = CM*y + CA

// ---------------------------------------------------------------------------
__global__ void qw_kernel() {
    int j = threadIdx.x;
    if (j > NQ) return;
    const float h = 5.0f / (float)NQ;
    float z = h * (float)j;
    float w = (j == 0 || j == NQ) ? 0.5f * h : h;
    g_qw[j] = 2.0f * INV_SQRT_2PI * w * __expf(-0.5f * z * z);
}

__global__ void table_val_kernel() {
    int i = threadIdx.x;
    if (i >= TBL_N) return;
    float y = ((float)i - CA) / CM;
    float s = 1.0f / (y * y) - 1.0f;
    if (s < 0.0f) s = 0.0f;
    float d = sqrtf(s);
    const float h = 5.0f / (float)NQ;
    float dz = d * h;
    float x = 0.0f;
    float acc = 0.0f;
    #pragma unroll 4
    for (int j = 0; j <= NQ; ++j) {
        float e = __expf(-2.0f * x);
        float inv = __fdividef(1.0f, 1.0f + e);
        acc = fmaf(g_qw[j], 4.0f * e * inv * inv, acc);
        x += dz;
    }
    g_val[i] = acc;
}

__global__ void table_coef_kernel() {
    int i = threadIdx.x;
    if (i >= TBL_N) return;
    float a;
    if (i == 0)              a = g_val[1] - g_val[0];
    else if (i == TBL_N - 1) a = g_val[TBL_N - 1] - g_val[TBL_N - 2];
    else                     a = 0.5f * (g_val[i + 1] - g_val[i - 1]);
    g_tab[i].x = a;
    g_tab[i].y = g_val[i] - a * (float)i;
}

// ---------------------------------------------------------------------------
// Scan: grid (32 rowblocks, 8 chunks) x 128 threads. 2 blocks/SM, 1 wave.
// Shared: replicated table float2[128][32] (32KB) + 2 overlay bufs 128*33 f.
// ---------------------------------------------------------------------------
__global__ __launch_bounds__(128, 2)
void scan_kernel(const float* __restrict__ u, float* __restrict__ out) {
    extern __shared__ float smem[];
    float2* s_tab = (float2*)smem;               // [128][32] float2
    float*  bufA  = smem + 2 * TBL_N * 32;       // 128*33 floats (u in / z out)
    float*  bufB  = bufA + 128 * 33;

    {   // replicate table: entry idx -> 32 lane copies
        float4* st = (float4*)s_tab;
        #pragma unroll 4
        for (int e = threadIdx.x; e < TBL_N * 16; e += 128) {
            float2 cc = __ldg(&g_tab[e >> 4]);
            st[e] = make_float4(cc.x, cc.y, cc.x, cc.y);
        }
    }
    __syncthreads();

    const int tid   = threadIdx.x;
    const int lane  = tid & 31;
    const int wbase = tid & ~31;
    const int la    = lane >> 3;     // row-in-4-group for coalesced loads
    const int lb    = lane & 7;      // t-chunk
    const int rowblk = blockIdx.x;
    const int c      = blockIdx.y;
    const int row    = rowblk * 128 + tid;

    // bits(idx + MAGIC)*256 mod 2^32 = 0x40000000 + 256*idx
    const unsigned tlane =
        (unsigned)__cvta_generic_to_shared(s_tab) + lane * 8u - 0x40000000u;

    const int t0 = c * LCH - (c ? WARM : 0);
    const int nwarm = c ? (WARM / 32) : 0;       // 6 or 0
    const int N     = nwarm + LCH / 32;          // 22 or 16 (even)

    // warp-coalesced u base: rows [rowblk*128+wbase .. +31]
    const float* ubase = u + (size_t)(rowblk * 128 + wbase) * T_DIM + t0;
    if (c == 0) out[(size_t)row * (T_DIM + 1)] = 0.0f;

    float K = 0.0f, v = 0.0f;
    float4 regA[8], regB[8];

    auto ldg = [&](float4 (&rg)[8], int g) {
        const float* gp = ubase + g * 32 + lb * 4;
        #pragma unroll
        for (int r = 0; r < 8; ++r)
            rg[r] = *(const float4*)(gp + (size_t)(la + 4 * r) * T_DIM);
    };
    auto sts = [&](float* buf, const float4 (&rg)[8]) {
        #pragma unroll
        for (int r = 0; r < 8; ++r) {            // banks la+4*lb: conflict-free
            float* q = buf + (wbase + la + 4 * r) * 33 + lb * 4;
            q[0] = rg[r].x; q[1] = rg[r].y; q[2] = rg[r].z; q[3] = rg[r].w;
        }
    };

    auto step = [&](float uu) {
        float up1 = fminf(fmaf(uu, uu, 1.0f), UP_CAP);  // off-chain
        v = fmaf(0.8f, v, 0.2f * uu);
        float w   = fmaf(0.28f, K, 0.52f * v);          // parallel w/ chain
        float K08 = 0.8f * K;
        float x   = fminf(fmaf(K, K, up1), X_CAP);      // x in [1, 85]
        float y;
        asm("rsqrt.approx.f32 %0, %1;" : "=f"(y) : "f"(x));
        float tf = fmaf(y, CM, CAM);                    // rounded idx + MAGIC
        float t  = fmaf(y, CM, CA);
        unsigned addr = __float_as_uint(tf) * 256u + tlane;
        float a, b2;
        asm volatile("ld.shared.v2.f32 {%0,%1}, [%2];"
                     : "=f"(a), "=f"(b2) : "r"(addr));
        float g = fmaf(t, a, b2);
        K = fmaf(g, w, K08);
    };

    auto compute = [&](float* buf) {             // u in-place -> z
        float* brow = buf + tid * 33;
        #pragma unroll
        for (int j = 0; j < 32; ++j) {
            float uu = brow[j];
            step(uu);
            brow[j] = 2.1f * K;
        }
    };
    auto flush = [&](const float* buf, int g) {  // coalesced z -> gmem
        int tg = t0 + g * 32;
        #pragma unroll 4
        for (int jr = 0; jr < 32; ++jr) {
            int grow = rowblk * 128 + wbase + jr;
            out[(size_t)grow * (T_DIM + 1) + 1 + tg + lane] =
                buf[(wbase + jr) * 33 + lane];
        }
    };

    ldg(regA, 0);
    #pragma unroll 1
    for (int g = 0; g < N; g += 2) {
        sts(bufA, regA);                 // commit group g
        ldg(regB, g + 1);                // prefetch g+1 (hidden by compute A)
        __syncwarp();
        compute(bufA);
        __syncwarp();
        if (g >= nwarm) flush(bufA, g);
        sts(bufB, regB);                 // commit g+1
        if (g + 2 < N) ldg(regA, g + 2); // prefetch g+2 (hidden by compute B)
        __syncwarp();
        compute(bufB);
        __syncwarp();
        if (g + 1 >= nwarm) flush(bufB, g + 1);
        __syncwarp();                    // flush reads done before next stsA
    }
}

// ---------------------------------------------------------------------------
extern "C" void kernel_launch(void* const* d_in, const int* in_sizes, int n_in,
                              void* d_out, int out_size) {
    const float* u = (const float*)d_in[0];
    float* out = (float*)d_out;

    static const int smem_bytes =
        2 * TBL_N * 32 * (int)sizeof(float) + 2 * 128 * 33 * (int)sizeof(float);
    cudaFuncSetAttribute(scan_kernel, cudaFuncAttributeMaxDynamicSharedMemorySize, smem_bytes);

    qw_kernel<<<1, 128>>>();
    table_val_kernel<<<1, TBL_N>>>();
    table_coef_kernel<<<1, TBL_N>>>();
    scan_kernel<<<dim3(B_DIM / 128, CHUNKS), 128, smem_bytes>>>(u, out);
}

// round 9
// speedup vs baseline: 1.4491x; 1.0585x over previous
#include <cuda_runtime.h>
#include <math.h>

// ---------------------------------------------------------------------------
// OneDimEquivalent scan, time-chunked (8 chunks x 512 steps, 128 warm-up).
//   v' = 0.8 v + 0.2 u ; k' = 0.8 k + g(k^2+u^2)*(0.28 k + 0.52 v') ; z = 2.1 k'
// g indexed in y = rsqrt(1+s), 128-cell LUT of line coeffs, lane-replicated
// 32x (zero-conflict LDS.64); x clamped to [1,85] -> index provably in
// [0,127]. u coalesced-loaded and staged through stride-36 smem overlay
// buffers; compute reads u via LDS.128 / writes z via STS.128 (4-step
// batches) to minimize LSU dispatch (the measured per-SM bottleneck).
// 256 blocks, 2/SM, single wave, 640 serial steps.
// ---------------------------------------------------------------------------

#define B_DIM 4096
#define T_DIM 4096
#define CHUNKS 8
#define LCH 512               // steps written per chunk
#define WARM 128              // warm-up steps for chunks c>0 (rho^128 ~ 1e-3 raw)
#define TBL_N 128
#define CM 142.4f             // t = CM*y + CA maps y in [0.108, 1] -> [0, 127]
#define CA (-15.38f)
#define MAGIC 12582912.0f     // 1.5 * 2^23
#define CAM (CA + MAGIC)
#define X_CAP 85.0f           // clamp on x = k^2+u^2+1 -> idx in [0,127] always
#define UP_CAP 65.0f          // off-chain clamp on u^2+1
#define INV_SQRT_2PI 0.3989422804014327f
#define NQ 96
#define BSTR 36               // overlay buffer row stride (floats): 16B-aligned

__device__ float  g_qw[NQ + 1];
__device__ float  g_val[TBL_N];
__device__ float2 g_tab[TBL_N];   // (a,b): g ~= a*t + b, t = CM*y + CA

// ---------------------------------------------------------------------------
__global__ void qw_kernel() {
    int j = threadIdx.x;
    if (j > NQ) return;
    const float h = 5.0f / (float)NQ;
    float z = h * (float)j;
    float w = (j == 0 || j == NQ) ? 0.5f * h : h;
    g_qw[j] = 2.0f * INV_SQRT_2PI * w * __expf(-0.5f * z * z);
}

__global__ void table_val_kernel() {
    int i = threadIdx.x;
    if (i >= TBL_N) return;
    float y = ((float)i - CA) / CM;
    float s = 1.0f / (y * y) - 1.0f;
    if (s < 0.0f) s = 0.0f;
    float d = sqrtf(s);
    const float h = 5.0f / (float)NQ;
    float dz = d * h;
    float x = 0.0f;
    float acc = 0.0f;
    #pragma unroll 4
    for (int j = 0; j <= NQ; ++j) {
        float e = __expf(-2.0f * x);
        float inv = __fdividef(1.0f, 1.0f + e);
        acc = fmaf(g_qw[j], 4.0f * e * inv * inv, acc);
        x += dz;
    }
    g_val[i] = acc;
}

__global__ void table_coef_kernel() {
    int i = threadIdx.x;
    if (i >= TBL_N) return;
    float a;
    if (i == 0)              a = g_val[1] - g_val[0];
    else if (i == TBL_N - 1) a = g_val[TBL_N - 1] - g_val[TBL_N - 2];
    else                     a = 0.5f * (g_val[i + 1] - g_val[i - 1]);
    g_tab[i].x = a;
    g_tab[i].y = g_val[i] - a * (float)i;
}

// ---------------------------------------------------------------------------
// Scan: grid (32 rowblocks, 8 chunks) x 128 threads. 2 blocks/SM, 1 wave.
// Shared: replicated table float2[128][32] (32KB) + 2 overlay bufs 128*36 f.
// ---------------------------------------------------------------------------
__global__ __launch_bounds__(128, 2)
void scan_kernel(const float* __restrict__ u, float* __restrict__ out) {
    extern __shared__ float smem[];
    float2* s_tab = (float2*)smem;               // [128][32] float2
    float*  bufA  = smem + 2 * TBL_N * 32;       // 128*BSTR floats (u in/z out)
    float*  bufB  = bufA + 128 * BSTR;

    {   // replicate table: entry idx -> 32 lane copies
        float4* st = (float4*)s_tab;
        #pragma unroll 4
        for (int e = threadIdx.x; e < TBL_N * 16; e += 128) {
            float2 cc = __ldg(&g_tab[e >> 4]);
            st[e] = make_float4(cc.x, cc.y, cc.x, cc.y);
        }
    }
    __syncthreads();

    const int tid   = threadIdx.x;
    const int lane  = tid & 31;
    const int wbase = tid & ~31;
    const int la    = lane >> 3;     // row-in-4-group for coalesced loads
    const int lb    = lane & 7;      // t-chunk
    const int rowblk = blockIdx.x;
    const int c      = blockIdx.y;
    const int row    = rowblk * 128 + tid;

    // bits(idx + MAGIC)*256 mod 2^32 = 0x40000000 + 256*idx
    const unsigned tlane =
        (unsigned)__cvta_generic_to_shared(s_tab) + lane * 8u - 0x40000000u;

    const int t0 = c * LCH - (c ? WARM : 0);
    const int nwarm = c ? (WARM / 32) : 0;       // 4 or 0
    const int N     = nwarm + LCH / 32;          // 20 or 16 (even)

    // warp-coalesced u base: rows [rowblk*128+wbase .. +31]
    const float* ubase = u + (size_t)(rowblk * 128 + wbase) * T_DIM + t0;
    if (c == 0) out[(size_t)row * (T_DIM + 1)] = 0.0f;

    float K = 0.0f, v = 0.0f;
    float4 regA[8], regB[8];

    auto ldg = [&](float4 (&rg)[8], int g) {
        const float* gp = ubase + g * 32 + lb * 4;
        #pragma unroll
        for (int r = 0; r < 8; ++r)
            rg[r] = *(const float4*)(gp + (size_t)(la + 4 * r) * T_DIM);
    };
    auto sts = [&](float* buf, const float4 (&rg)[8]) {
        #pragma unroll
        for (int r = 0; r < 8; ++r) {            // octet-phase conflict-free
            float4* q = (float4*)(buf + (wbase + la + 4 * r) * BSTR + lb * 4);
            *q = rg[r];
        }
    };

    auto step = [&](float uu) {
        float up1 = fminf(fmaf(uu, uu, 1.0f), UP_CAP);  // off-chain
        v = fmaf(0.8f, v, 0.2f * uu);
        float w   = fmaf(0.28f, K, 0.52f * v);          // parallel w/ chain
        float K08 = 0.8f * K;
        float x   = fminf(fmaf(K, K, up1), X_CAP);      // x in [1, 85]
        float y;
        asm("rsqrt.approx.f32 %0, %1;" : "=f"(y) : "f"(x));
        float tf = fmaf(y, CM, CAM);                    // rounded idx + MAGIC
        float t  = fmaf(y, CM, CA);
        unsigned addr = __float_as_uint(tf) * 256u + tlane;
        float a, b2;
        asm volatile("ld.shared.v2.f32 {%0,%1}, [%2];"
                     : "=f"(a), "=f"(b2) : "r"(addr));
        float g = fmaf(t, a, b2);
        K = fmaf(g, w, K08);
    };

    auto compute = [&](float* buf) {             // u in-place -> z, 4-batched
        float* brow = buf + tid * BSTR;
        #pragma unroll
        for (int j4 = 0; j4 < 8; ++j4) {
            float4 u4 = *(float4*)(brow + j4 * 4);   // LDS.128
            float4 z4;
            step(u4.x); z4.x = 2.1f * K;
            step(u4.y); z4.y = 2.1f * K;
            step(u4.z); z4.z = 2.1f * K;
            step(u4.w); z4.w = 2.1f * K;
            *(float4*)(brow + j4 * 4) = z4;          // STS.128
        }
    };
    auto flush = [&](const float* buf, int g) {  // coalesced z -> gmem
        int tg = t0 + g * 32;
        #pragma unroll 4
        for (int jr = 0; jr < 32; ++jr) {
            int grow = rowblk * 128 + wbase + jr;
            out[(size_t)grow * (T_DIM + 1) + 1 + tg + lane] =
                buf[(wbase + jr) * BSTR + lane];
        }
    };

    ldg(regA, 0);
    #pragma unroll 1
    for (int g = 0; g < N; g += 2) {
        sts(bufA, regA);                 // commit group g
        ldg(regB, g + 1);                // prefetch g+1 (hidden by compute A)
        __syncwarp();
        compute(bufA);
        __syncwarp();
        if (g >= nwarm) flush(bufA, g);
        sts(bufB, regB);                 // commit g+1
        if (g + 2 < N) ldg(regA, g + 2); // prefetch g+2 (hidden by compute B)
        __syncwarp();
        compute(bufB);
        __syncwarp();
        if (g + 1 >= nwarm) flush(bufB, g + 1);
        __syncwarp();                    // flush reads done before next stsA
    }
}

// ---------------------------------------------------------------------------
extern "C" void kernel_launch(void* const* d_in, const int* in_sizes, int n_in,
                              void* d_out, int out_size) {
    const float* u = (const float*)d_in[0];
    float* out = (float*)d_out;

    static const int smem_bytes =
        2 * TBL_N * 32 * (int)sizeof(float) + 2 * 128 * BSTR * (int)sizeof(float);
    cudaFuncSetAttribute(scan_kernel, cudaFuncAttributeMaxDynamicSharedMemorySize, smem_bytes);

    qw_kernel<<<1, 128>>>();
    table_val_kernel<<<1, TBL_N>>>();
    table_coef_kernel<<<1, TBL_N>>>();
    scan_kernel<<<dim3(B_DIM / 128, CHUNKS), 128, smem_bytes>>>(u, out);
}